// round 6
// baseline (speedup 1.0000x reference)
#include <cuda_runtime.h>
#include <cuda_bf16.h>

// Problem dims
#define BATCH  64
#define SDIM   4096
#define DDIM   256
#define SCHUNK 512
#define NCHUNK (SDIM / SCHUNK)          // 8
#define NBLK   (BATCH * NCHUNK)         // 512 CTAs — single wave at occ 4

#define TROWS  16                        // rows per smem tile (16 KB)
#define NTILE  (SCHUNK / TROWS)          // 32 tiles per CTA
#define TF4    (TROWS * 64)              // float4s per tile = 1024

// Scratch for cross-CTA partials (no allocation allowed -> device globals)
__device__ float g_acc[NBLK * DDIM];    // 512 KB
__device__ float g_sum[NBLK];
__device__ int   g_cnt[BATCH];          // zero-init; re-armed by finalizer each run

__device__ __forceinline__ float warp_sum(float v) {
    #pragma unroll
    for (int o = 16; o; o >>= 1) v += __shfl_xor_sync(0xffffffffu, v, o);
    return v;
}

__device__ __forceinline__ void cp_async16(void* smem, const void* gmem) {
    unsigned sa = (unsigned)__cvta_generic_to_shared(smem);
    asm volatile("cp.async.cg.shared.global [%0], [%1], 16;" :: "r"(sa), "l"(gmem));
}
__device__ __forceinline__ void cp_commit() {
    asm volatile("cp.async.commit_group;");
}
template<int N> __device__ __forceinline__ void cp_wait() {
    asm volatile("cp.async.wait_group %0;" :: "n"(N));
}

// ---------------------------------------------------------------------------
// Single pass over memory (268 MB read exactly once):
//   gi = tanh(m·Wm + c_b) in [-1,1] => exp never overflows => softmax needs
//   no running max; accumulate exp(gi)*m and exp(gi) in one sweep.
// Loads DECOUPLED from compute via cp.async double-buffered smem tiles.
// Pipeline ledger: at start of iter t pending groups = {t, t+1};
//   wait_group 1 -> tile t resident.  LAST iter has pending = {NTILE-1}
//   only, so it must use wait_group 0 (R5 bug: wait<1> passed early).
// Last CTA per batch finalizes the output (threadfence-reduction pattern).
// ---------------------------------------------------------------------------
__global__ __launch_bounds__(256, 4)
void att_fused(const float* __restrict__ memory,
               const float* __restrict__ aspect,
               const float* __restrict__ W,
               const float* __restrict__ bias,
               float* __restrict__ out)
{
    __shared__ float4 sbuf[2][TF4];      // 2 x 16 KB tile buffers
    __shared__ float  sacc[DDIM];
    __shared__ float  ssum;
    __shared__ float  sc;
    __shared__ int    s_old;

    const int tid  = threadIdx.x;
    const int lane = tid & 31;
    const int warp = tid >> 5;
    const int blk  = blockIdx.x;
    const int b    = blk >> 3;       // / NCHUNK
    const int chnk = blk & (NCHUNK - 1);

    // ---- c_b = aspect[b]·Wa + bias ----
    {
        float v = warp_sum(aspect[b * DDIM + tid] * W[DDIM + tid]);
        if (tid == 0) { ssum = 0.f; sc = bias[0]; }
        sacc[tid] = 0.f;
        __syncthreads();
        if (lane == 0) atomicAdd(&sc, v);
        __syncthreads();
    }
    const float cb = sc;

    // ---- Wm slice in registers: lane covers d = 4*lane.. and 128+4*lane.. ----
    const float4 wm0 = *reinterpret_cast<const float4*>(W + 4 * lane);
    const float4 wm1 = *reinterpret_cast<const float4*>(W + 128 + 4 * lane);

    float4 a0 = make_float4(0.f, 0.f, 0.f, 0.f);
    float4 a1 = make_float4(0.f, 0.f, 0.f, 0.f);
    float  sw = 0.f;

    const float4* base = reinterpret_cast<const float4*>(
        memory + ((long)b * SDIM + (long)chnk * SCHUNK) * DDIM);

    // ---- issue helper: thread copies 4 x 16B chunks of the 16 KB tile ----
    auto issue_tile = [&](int t, int bi) {
        const float4* g = base + (long)t * TF4 + tid;
        float4*       s = &sbuf[bi][tid];
        #pragma unroll
        for (int j = 0; j < 4; j++)
            cp_async16(s + 256 * j, g + 256 * j);
        cp_commit();
    };

    // prologue: tiles 0,1 in flight
    issue_tile(0, 0);
    issue_tile(1, 1);

    for (int t = 0; t < NTILE; t++) {
        const int bi = t & 1;
        if (t == NTILE - 1) cp_wait<0>();   // drain: last tile's group is the only one left
        else                cp_wait<1>();   // tile t resident (t+1 may still fly)
        __syncthreads();

        // ---- compute tile t from smem: warp handles rows warp, warp+8 ----
        const float4* r0 = &sbuf[bi][(warp)     * 64];
        const float4* r1 = &sbuf[bi][(warp + 8) * 64];
        const float4 m00 = r0[lane], m01 = r0[32 + lane];
        const float4 m10 = r1[lane], m11 = r1[32 + lane];

        float d0 = m00.x * wm0.x + m00.y * wm0.y + m00.z * wm0.z + m00.w * wm0.w
                 + m01.x * wm1.x + m01.y * wm1.y + m01.z * wm1.z + m01.w * wm1.w;
        float d1 = m10.x * wm0.x + m10.y * wm0.y + m10.z * wm0.z + m10.w * wm0.w
                 + m11.x * wm1.x + m11.y * wm1.y + m11.z * wm1.z + m11.w * wm1.w;
        d0 = warp_sum(d0);
        d1 = warp_sum(d1);
        const float w0 = __expf(tanhf(d0 + cb));
        const float w1 = __expf(tanhf(d1 + cb));

        a0.x += w0 * m00.x + w1 * m10.x;  a0.y += w0 * m00.y + w1 * m10.y;
        a0.z += w0 * m00.z + w1 * m10.z;  a0.w += w0 * m00.w + w1 * m10.w;
        a1.x += w0 * m01.x + w1 * m11.x;  a1.y += w0 * m01.y + w1 * m11.y;
        a1.z += w0 * m01.z + w1 * m11.z;  a1.w += w0 * m01.w + w1 * m11.w;
        sw   += w0 + w1;                  // uniform across lanes post-butterfly

        __syncthreads();                  // everyone done reading buf[bi]
        if (t + 2 < NTILE) issue_tile(t + 2, bi);
    }

    // ---- combine 8 warps via smem atomics (spread addresses, cheap) ----
    atomicAdd(&sacc[4 * lane + 0], a0.x);
    atomicAdd(&sacc[4 * lane + 1], a0.y);
    atomicAdd(&sacc[4 * lane + 2], a0.z);
    atomicAdd(&sacc[4 * lane + 3], a0.w);
    atomicAdd(&sacc[128 + 4 * lane + 0], a1.x);
    atomicAdd(&sacc[128 + 4 * lane + 1], a1.y);
    atomicAdd(&sacc[128 + 4 * lane + 2], a1.z);
    atomicAdd(&sacc[128 + 4 * lane + 3], a1.w);
    if (lane == 0) atomicAdd(&ssum, sw);
    __syncthreads();

    g_acc[blk * DDIM + tid] = sacc[tid];
    if (tid == 0) g_sum[blk] = ssum;
    __syncthreads();

    // ---- last-CTA-per-batch finalize ----
    if (tid == 0) {
        __threadfence();
        s_old = atomicAdd(&g_cnt[b], 1);
    }
    __syncthreads();
    if (s_old == NCHUNK - 1) {
        __threadfence();                 // acquire siblings' partials
        float acc = 0.f, s = 0.f;
        #pragma unroll
        for (int c = 0; c < NCHUNK; c++) {
            acc += g_acc[(b * NCHUNK + c) * DDIM + tid];
            s   += g_sum[b * NCHUNK + c];
        }
        out[b * DDIM + tid] = acc / s;
        __syncthreads();
        if (tid == 0) g_cnt[b] = 0;      // re-arm for next graph replay
    }
}

extern "C" void kernel_launch(void* const* d_in, const int* in_sizes, int n_in,
                              void* d_out, int out_size)
{
    // Map inputs by element count:
    //   memory: B*S*D = 67108864, aspect: B*D = 16384, W: 2*D = 512, b: 1
    const float *aspect = nullptr, *memory = nullptr, *W = nullptr, *bias = nullptr;
    for (int i = 0; i < n_in; i++) {
        const long n = (long)in_sizes[i];
        const float* p = (const float*)d_in[i];
        if      (n == (long)BATCH * SDIM * DDIM) memory = p;
        else if (n == (long)BATCH * DDIM)        aspect = p;
        else if (n == 2 * DDIM)                  W      = p;
        else if (n == 1)                         bias   = p;
    }

    att_fused<<<NBLK, 256>>>(memory, aspect, W, bias, (float*)d_out);
}